// round 12
// baseline (speedup 1.0000x reference)
#include <cuda_runtime.h>
#include <cstdint>

// RecallLoss: input [N=8, C=21, H=512, W=512] f32, target [N,H,W] int64/int32
// (auto-detected). loss = 1 - mean_{n,c} (tp+eps)/(tt+eps).
//
// Register-free load depth via cp.async staging in DYNAMIC shared memory.
// Each thread stages its 21 channel float4s via cp.async.cg (10.5KB in flight
// per warp, independent of register count), waits on its own group
// (per-thread wait_group 0 — no block sync in the hot path), computes from
// smem. Model from R3-R9: DRAM% tracks in-flight-bytes/~11.8KB per SM; LDG
// variants cap at ~7.4KB (register-bound MLP). cp.async breaks that cap.

#define SMOOTH 1e-5f

constexpr int N_IMG  = 8;
constexpr int C_CLS  = 21;
constexpr int HW     = 512 * 512;       // 262144 positions per image
constexpr int NC     = N_IMG * C_CLS;   // 168 bins
constexpr int TPB    = 256;
constexpr int IPT    = 4;               // positions per thread (float4)
constexpr int BLKS_PER_IMG = HW / (TPB * IPT);   // 256
constexpr int GRID   = N_IMG * BLKS_PER_IMG;     // 2048
constexpr int NWARP  = TPB / 32;        // 8

constexpr int DYN_BYTES = NWARP * C_CLS * 32 * 16;   // 86016 = 84KB

// Zero-initialized at module load; finishing block re-zeroes after each
// launch so every graph replay starts clean.
__device__ int g_tp[NC];
__device__ int g_tt[NC];
__device__ unsigned int g_arrive;

__device__ __forceinline__ unsigned smem_u32(const void* p) {
    return (unsigned)__cvta_generic_to_shared(p);
}
__device__ __forceinline__ void cp_async16(void* dst_smem, const void* src) {
    asm volatile("cp.async.cg.shared.global [%0], [%1], 16;"
                 :: "r"(smem_u32(dst_smem)), "l"(src) : "memory");
}
__device__ __forceinline__ void cp_commit() {
    asm volatile("cp.async.commit_group;" ::: "memory");
}
__device__ __forceinline__ void cp_wait_all() {
    asm volatile("cp.async.wait_group 0;" ::: "memory");
}

// Warp-aggregated count: leaders of distinct classes touch distinct words of
// the warp-private row, so one plain LDS+IADD+STS per call replaces atomics.
__device__ __forceinline__ void warp_count(
    unsigned int* __restrict__ cnt, int bin, int pred_match, int lid)
{
    unsigned int grp = __match_any_sync(0xffffffffu, bin);
    unsigned int mb  = __ballot_sync(0xffffffffu, pred_match);
    unsigned int add = __popc(grp) + (__popc(grp & mb) << 16);
    if ((grp & ((1u << lid) - 1u)) == 0u)
        cnt[bin] += add;
}

__global__ __launch_bounds__(TPB) void recall_fused_kernel(
    const float* __restrict__ inp, const void* __restrict__ tgt_raw,
    float* __restrict__ out)
{
    // Dynamic staging buffer, layout [warp][channel][lane] float4:
    // lane-consecutive 16B chunks -> GMEM 512B/warp/channel contiguous,
    // LDS.128 conflict-free reads.
    extern __shared__ float4 dynbuf[];
    __shared__ unsigned int s_cnt[NWARP][C_CLS];   // packed tp<<16 | tt
    __shared__ int s_is64;
    __shared__ float s_red[NWARP];

    const int tid = threadIdx.x;
    const int wid = tid >> 5;
    const int lid = tid & 31;
    if (lid < C_CLS) s_cnt[wid][lid] = 0;

    // dtype detect: int64 targets in [0,21) have all-zero odd 32-bit words;
    // for int32 the chance 16 specific odd words are all 0 is (1/21)^16 ~ 0.
    if (tid == 0) {
        const int* w = (const int*)tgt_raw;
        int is64 = 1;
        #pragma unroll
        for (int k = 0; k < 16; k++) is64 &= (w[2 * k + 1] == 0);
        s_is64 = is64;
    }
    __syncthreads();   // s_is64 + s_cnt visible; only pre-reduce block sync

    const int n   = blockIdx.x >> 8;         // BLKS_PER_IMG = 256
    const int blk = blockIdx.x & 255;
    const int l0  = blk * (TPB * IPT) + tid * IPT;      // < 2^18

    float4* const my_buf = dynbuf + (wid * C_CLS * 32 + lid);  // [+c*32] per ch

    // ---- stage: 21 cp.asyncs, 10.5KB in flight per warp --------------------
    const float* src = inp + (n * C_CLS * HW + l0);
    #pragma unroll
    for (int c = 0; c < C_CLS; c++) {
        cp_async16(my_buf + c * 32, src + c * HW);
    }
    cp_commit();

    // Target loads overlap the cp.async wait (independent of smem).
    int t0, t1, t2, t3;
    if (s_is64) {
        const long long* tp = (const long long*)tgt_raw + (n * HW + l0);
        longlong2 a = __ldcs(reinterpret_cast<const longlong2*>(tp));
        longlong2 b = __ldcs(reinterpret_cast<const longlong2*>(tp + 2));
        t0 = (int)a.x; t1 = (int)a.y; t2 = (int)b.x; t3 = (int)b.y;
    } else {
        const int* tp = (const int*)tgt_raw + (n * HW + l0);
        int4 a = __ldcs(reinterpret_cast<const int4*>(tp));
        t0 = a.x; t1 = a.y; t2 = a.z; t3 = a.w;
    }

    // Per-thread wait: this thread consumes ONLY bytes it staged itself, so
    // wait_group(0) suffices — no __syncthreads, warps free-run.
    cp_wait_all();

    // ---- argmax over 21 channels (channel 0 seeds; strict > = first-index
    // tie semantics, matching jnp.argmax) ------------------------------------
    float4 v = my_buf[0];
    float m0 = v.x, m1 = v.y, m2 = v.z, m3 = v.w;
    int   i0 = 0,  i1 = 0,  i2 = 0,  i3 = 0;
    #pragma unroll
    for (int c = 1; c < C_CLS; c++) {
        float4 u = my_buf[c * 32];
        if (u.x > m0) { m0 = u.x; i0 = c; }
        if (u.y > m1) { m1 = u.y; i1 = c; }
        if (u.z > m2) { m2 = u.z; i2 = c; }
        if (u.w > m3) { m3 = u.w; i3 = c; }
    }

    unsigned int* const cnt = s_cnt[wid];
    warp_count(cnt, t0, i0 == t0, lid);
    warp_count(cnt, t1, i1 == t1, lid);
    warp_count(cnt, t2, i2 == t2, lid);
    warp_count(cnt, t3, i3 == t3, lid);

    __syncthreads();

    // Block reduce: 21 bins, sum 8 warp rows, one global atomic pair each.
    if (tid < C_CLS) {
        unsigned int a = 0;
        #pragma unroll
        for (int w = 0; w < NWARP; w++) a += s_cnt[w][tid];
        atomicAdd(&g_tt[n * C_CLS + tid], (int)(a & 0xFFFFu));
        atomicAdd(&g_tp[n * C_CLS + tid], (int)(a >> 16));
    }

    // ---- last-block epilogue -------------------------------------------
    __shared__ int s_last;
    __threadfence();   // release this block's counter contributions
    if (tid == 0) {
        unsigned int old = atomicAdd(&g_arrive, 1u);
        s_last = (old == (unsigned int)(GRID - 1));
    }
    __syncthreads();
    if (!s_last) return;

    __threadfence();   // acquire all blocks' contributions
    float r = 0.0f;
    if (tid < NC) {
        r = ((float)g_tp[tid] + SMOOTH) / ((float)g_tt[tid] + SMOOTH);
    }
    #pragma unroll
    for (int o = 16; o > 0; o >>= 1) r += __shfl_down_sync(0xffffffffu, r, o);
    if (lid == 0) s_red[wid] = r;
    __syncthreads();
    if (tid == 0) {
        float s = 0.0f;
        #pragma unroll
        for (int w = 0; w < NWARP; w++) s += s_red[w];
        out[0] = 1.0f - s / (float)NC;
    }

    // Reset state for the next graph replay.
    if (tid < NC) { g_tp[tid] = 0; g_tt[tid] = 0; }
    if (tid == 0) g_arrive = 0u;
}

extern "C" void kernel_launch(void* const* d_in, const int* in_sizes, int n_in,
                              void* d_out, int out_size) {
    const float* inp = (const float*)d_in[0];
    const void*  tgt = d_in[1];
    float* out = (float*)d_out;

    // Sticky function attribute; deterministic, capture-safe (no stream work).
    cudaFuncSetAttribute(recall_fused_kernel,
                         cudaFuncAttributeMaxDynamicSharedMemorySize,
                         DYN_BYTES);

    recall_fused_kernel<<<GRID, TPB, DYN_BYTES>>>(inp, tgt, out);
}

// round 15
// speedup vs baseline: 1.3739x; 1.3739x over previous
#include <cuda_runtime.h>
#include <cstdint>

// RecallLoss: input [N=8, C=21, H=512, W=512] f32, target [N, H, W] int64 (or
// int32 — auto-detected). loss = 1 - mean_{n,c} (tp+eps)/(tt+eps).
//
// Proven R3 streaming core (float4 LDG.128, __ldcs, 32 regs, max occ, plain
// packed smem atomics) with TPB=512/grid=1024: half the per-block fixed
// costs, identical per-thread work and occupancy. Empirical record R3-R12:
// occupancy dominates DRAM%; structural interventions (match_any, cp.async
// staging, channel-major ordering, persistent blocks) all neutral or worse.

#define SMOOTH 1e-5f

constexpr int N_IMG  = 8;
constexpr int C_CLS  = 21;
constexpr int HW     = 512 * 512;       // 262144 positions per image
constexpr int NC     = N_IMG * C_CLS;   // 168 bins
constexpr int TPB    = 512;
constexpr int IPT    = 4;               // positions per thread (float4)
constexpr int BLKS_PER_IMG = HW / (TPB * IPT);   // 128
constexpr int GRID   = N_IMG * BLKS_PER_IMG;     // 1024
constexpr int NWARP  = TPB / 32;        // 16

// Zero-initialized at module load; the finishing block re-zeroes after each
// launch so every graph replay starts clean.
__device__ int g_tp[NC];
__device__ int g_tt[NC];
__device__ unsigned int g_arrive;

__global__ __launch_bounds__(TPB) void recall_fused_kernel(
    const float* __restrict__ inp, const void* __restrict__ tgt_raw,
    float* __restrict__ out)
{
    // Per-warp packed counters: bits[15:0]=tt, bits[31:16]=tp.
    // Max per bin per warp = 32 lanes * 4 positions = 128 << 65536.
    __shared__ unsigned int s_cnt[NWARP][C_CLS];
    __shared__ int s_is64;
    __shared__ float s_red[NWARP];

    const int wid = threadIdx.x >> 5;
    const int lid = threadIdx.x & 31;
    if (lid < C_CLS) s_cnt[wid][lid] = 0;

    // dtype detect: int64 targets in [0,21) have all-zero odd 32-bit words;
    // for int32 the chance 16 specific odd words are all 0 is (1/21)^16 ~ 0.
    if (threadIdx.x == 0) {
        const int* w = (const int*)tgt_raw;
        int is64 = 1;
        #pragma unroll
        for (int k = 0; k < 16; k++) is64 &= (w[2 * k + 1] == 0);
        s_is64 = is64;
    }
    __syncthreads();

    const int n   = blockIdx.x >> 7;         // BLKS_PER_IMG = 128
    const int blk = blockIdx.x & 127;
    const int l0  = blk * (TPB * IPT) + threadIdx.x * IPT;   // < 2^18

    // All-32-bit offsets: max element index 8*21*262144 = 44M < 2^31.
    const float* base = inp + (n * C_CLS * HW + l0);

    // Channel 0 seeds; strict > keeps first max index (jnp.argmax ties).
    // __ldcs: single-touch streaming data, evict-first.
    float4 v = __ldcs(reinterpret_cast<const float4*>(base));
    float m0 = v.x, m1 = v.y, m2 = v.z, m3 = v.w;
    int   i0 = 0,  i1 = 0,  i2 = 0,  i3 = 0;

    #pragma unroll
    for (int c = 1; c < C_CLS; c++) {
        float4 u = __ldcs(reinterpret_cast<const float4*>(base + c * HW));
        if (u.x > m0) { m0 = u.x; i0 = c; }
        if (u.y > m1) { m1 = u.y; i1 = c; }
        if (u.z > m2) { m2 = u.z; i2 = c; }
        if (u.w > m3) { m3 = u.w; i3 = c; }
    }

    int t0, t1, t2, t3;
    if (s_is64) {
        const long long* tp = (const long long*)tgt_raw + (n * HW + l0);
        longlong2 a = __ldcs(reinterpret_cast<const longlong2*>(tp));
        longlong2 b = __ldcs(reinterpret_cast<const longlong2*>(tp + 2));
        t0 = (int)a.x; t1 = (int)a.y; t2 = (int)b.x; t3 = (int)b.y;
    } else {
        const int* tp = (const int*)tgt_raw + (n * HW + l0);
        int4 a = __ldcs(reinterpret_cast<const int4*>(tp));
        t0 = a.x; t1 = a.y; t2 = a.z; t3 = a.w;
    }

    // Packed counter update: +1 (tt) and +(1<<16) when argmax matched (tp).
    unsigned int* const cnt = s_cnt[wid];
    atomicAdd(&cnt[t0], 1u + (i0 == t0 ? 0x10000u : 0u));
    atomicAdd(&cnt[t1], 1u + (i1 == t1 ? 0x10000u : 0u));
    atomicAdd(&cnt[t2], 1u + (i2 == t2 ? 0x10000u : 0u));
    atomicAdd(&cnt[t3], 1u + (i3 == t3 ? 0x10000u : 0u));

    __syncthreads();

    // Block reduce: 21 bins, sum 16 warp rows, one global atomic pair each.
    if (threadIdx.x < C_CLS) {
        unsigned int a = 0;
        #pragma unroll
        for (int w = 0; w < NWARP; w++) a += s_cnt[w][threadIdx.x];
        atomicAdd(&g_tt[n * C_CLS + threadIdx.x], (int)(a & 0xFFFFu));
        atomicAdd(&g_tp[n * C_CLS + threadIdx.x], (int)(a >> 16));
    }

    // ---- last-block epilogue -------------------------------------------
    __shared__ int s_last;
    __threadfence();   // release this block's counter contributions
    if (threadIdx.x == 0) {
        unsigned int old = atomicAdd(&g_arrive, 1u);
        s_last = (old == (unsigned int)(GRID - 1));
    }
    __syncthreads();
    if (!s_last) return;

    __threadfence();   // acquire all blocks' contributions
    const int i = threadIdx.x;
    float r = 0.0f;
    if (i < NC) {
        r = ((float)g_tp[i] + SMOOTH) / ((float)g_tt[i] + SMOOTH);
    }
    #pragma unroll
    for (int o = 16; o > 0; o >>= 1) r += __shfl_down_sync(0xffffffffu, r, o);
    if (lid == 0) s_red[wid] = r;
    __syncthreads();
    if (i == 0) {
        float s = 0.0f;
        #pragma unroll
        for (int w = 0; w < NWARP; w++) s += s_red[w];
        out[0] = 1.0f - s / (float)NC;
    }

    // Reset state for the next graph replay.
    if (i < NC) { g_tp[i] = 0; g_tt[i] = 0; }
    if (i == 0) g_arrive = 0u;
}

extern "C" void kernel_launch(void* const* d_in, const int* in_sizes, int n_in,
                              void* d_out, int out_size) {
    const float* inp = (const float*)d_in[0];
    const void*  tgt = d_in[1];
    float* out = (float*)d_out;

    recall_fused_kernel<<<GRID, TPB>>>(inp, tgt, out);
}